// round 4
// baseline (speedup 1.0000x reference)
#include <cuda_runtime.h>
#include <cuda_bf16.h>
#include <cstdint>

#define BATCH 4
#define SEQ 2048
#define DIM 1024
#define HEADS 16
#define DHEAD 64
#define INNER 1024
#define ROWS (BATCH * SEQ)      /* 8192 */
#define QKV_COLS (3 * INNER)    /* 3072 */
#define ATT_SCALE 0.125f

// ---------------- scratch (device globals) ----------------------------------
__device__ __nv_bfloat16 g_xh[(size_t)ROWS * DIM];
__device__ __nv_bfloat16 g_xl[(size_t)ROWS * DIM];
__device__ __nv_bfloat16 g_qkvh[(size_t)ROWS * QKV_COLS];
__device__ __nv_bfloat16 g_qkvl[(size_t)ROWS * QKV_COLS];
__device__ __nv_bfloat16 g_oh[(size_t)ROWS * INNER];
__device__ __nv_bfloat16 g_ol[(size_t)ROWS * INNER];
__device__ __nv_bfloat16 g_wqkvh[(size_t)QKV_COLS * DIM];  // [N][K]
__device__ __nv_bfloat16 g_wqkvl[(size_t)QKV_COLS * DIM];
__device__ __nv_bfloat16 g_wouth[(size_t)DIM * INNER];     // [N][K]
__device__ __nv_bfloat16 g_woutl[(size_t)DIM * INNER];

// ---------------------------------------------------------------------------
__device__ __forceinline__ void split_pack(float f0, float f1,
                                           uint32_t& hi, uint32_t& lo) {
    __nv_bfloat16 h0 = __float2bfloat16(f0), h1 = __float2bfloat16(f1);
    float r0 = f0 - __bfloat162float(h0), r1 = f1 - __bfloat162float(h1);
    hi = (uint32_t)__bfloat16_as_ushort(h0) |
         ((uint32_t)__bfloat16_as_ushort(h1) << 16);
    lo = (uint32_t)__bfloat16_as_ushort(__float2bfloat16(r0)) |
         ((uint32_t)__bfloat16_as_ushort(__float2bfloat16(r1)) << 16);
}

__global__ void split_f32(const float* __restrict__ in,
                          __nv_bfloat16* __restrict__ hi,
                          __nv_bfloat16* __restrict__ lo, int n4)
{
    int i = blockIdx.x * blockDim.x + threadIdx.x;
    if (i >= n4) return;
    float4 v = ((const float4*)in)[i];
    uint32_t h0, l0, h1, l1;
    split_pack(v.x, v.y, h0, l0);
    split_pack(v.z, v.w, h1, l1);
    ((uint2*)hi)[i] = make_uint2(h0, h1);
    ((uint2*)lo)[i] = make_uint2(l0, l1);
}

__global__ void transpose_split(const float* __restrict__ W,
                                __nv_bfloat16* __restrict__ Th,
                                __nv_bfloat16* __restrict__ Tl, int K, int N)
{
    __shared__ float t[32][33];
    int k0 = blockIdx.y * 32, n0 = blockIdx.x * 32;
    int tx = threadIdx.x, ty = threadIdx.y;
#pragma unroll
    for (int j = 0; j < 4; j++)
        t[ty + j * 8][tx] = W[(size_t)(k0 + ty + j * 8) * N + n0 + tx];
    __syncthreads();
#pragma unroll
    for (int j = 0; j < 4; j++) {
        float f = t[tx][ty + j * 8];
        __nv_bfloat16 h = __float2bfloat16(f);
        __nv_bfloat16 l = __float2bfloat16(f - __bfloat162float(h));
        size_t o = (size_t)(n0 + ty + j * 8) * K + k0 + tx;
        Th[o] = h;
        Tl[o] = l;
    }
}

// ---------------------------------------------------------------------------
#define LDSM4(r0, r1, r2, r3, addr)                                          \
    asm volatile("ldmatrix.sync.aligned.m8n8.x4.shared.b16 {%0,%1,%2,%3}, [%4];" \
                 : "=r"(r0), "=r"(r1), "=r"(r2), "=r"(r3) : "r"(addr))
#define LDSM4T(r0, r1, r2, r3, addr)                                         \
    asm volatile("ldmatrix.sync.aligned.m8n8.x4.trans.shared.b16 {%0,%1,%2,%3}, [%4];" \
                 : "=r"(r0), "=r"(r1), "=r"(r2), "=r"(r3) : "r"(addr))
#define MMA16816(d, a, b)                                                    \
    asm volatile("mma.sync.aligned.m16n8k16.row.col.f32.bf16.bf16.f32 "      \
                 "{%0,%1,%2,%3},{%4,%5,%6,%7},{%8,%9},{%0,%1,%2,%3};"        \
                 : "+f"(d[0]), "+f"(d[1]), "+f"(d[2]), "+f"(d[3])            \
                 : "r"(a[0]), "r"(a[1]), "r"(a[2]), "r"(a[3]),               \
                   "r"(b[0]), "r"(b[1]))
#define MMAS(d, a0, a1, a2, a3, b0, b1)                                      \
    asm volatile("mma.sync.aligned.m16n8k16.row.col.f32.bf16.bf16.f32 "      \
                 "{%0,%1,%2,%3},{%4,%5,%6,%7},{%8,%9},{%0,%1,%2,%3};"        \
                 : "+f"(d[0]), "+f"(d[1]), "+f"(d[2]), "+f"(d[3])            \
                 : "r"(a0), "r"(a1), "r"(a2), "r"(a3), "r"(b0), "r"(b1))
#define CPASYNC16(dst, src)                                                  \
    asm volatile("cp.async.cg.shared.global [%0], [%1], 16;" :: "r"(dst), "l"(src))

// ---------------------------------------------------------------------------
// bf16x3 GEMM, 3-stage cp.async pipeline, term-major MMA ordering.
// ---------------------------------------------------------------------------
#define GBM 128
#define GBN 128
#define GBK 32
#define GKP 40
#define GSTAGE (4 * GBM * GKP)
#define NSTG 3
#define GSMEM (NSTG * GSTAGE * 2)

template <bool SPLIT_OUT>
__global__ __launch_bounds__(256, 1) void gemm_bf16x3(
    const __nv_bfloat16* __restrict__ Ah, const __nv_bfloat16* __restrict__ Al,
    const __nv_bfloat16* __restrict__ Bh, const __nv_bfloat16* __restrict__ Bl,
    const float* __restrict__ bias, float* __restrict__ C,
    __nv_bfloat16* __restrict__ Chi, __nv_bfloat16* __restrict__ Clo,
    int M, int N, int K)
{
    extern __shared__ __nv_bfloat16 sm[];
    const int tid = threadIdx.x;
    const int lane = tid & 31, warp = tid >> 5;
    const int wm = warp >> 1, wn = warp & 1;
    const int brow = blockIdx.y * GBM, bcol = blockIdx.x * GBN;

    uint32_t sbase = (uint32_t)__cvta_generic_to_shared(sm);
    const int lrow = tid >> 2;
    const int lk = (tid & 3) << 3;

    const __nv_bfloat16* gA[2] = {Ah, Al};
    const __nv_bfloat16* gB[2] = {Bh, Bl};
    float acc[2][8][4] = {};

    const int a_r = lane & 15;
    const int a_k = (lane >> 4) << 3;
    const int bg = lane >> 3;
    const int b_r = ((bg & 2) << 2) + (lane & 7);
    const int b_k = (bg & 1) << 3;
    const int NK = K / GBK;

    auto load_stage = [&](int st, int k0) {
        int base = st * GSTAGE;
#pragma unroll
        for (int v = 0; v < 2; v++) {
#pragma unroll
            for (int i = 0; i < 2; i++) {
                int row = lrow + i * 64;
                uint32_t da = sbase + (uint32_t)(base + v * GBM * GKP + row * GKP + lk) * 2;
                CPASYNC16(da, gA[v] + (size_t)(brow + row) * K + k0 + lk);
                uint32_t db = sbase + (uint32_t)(base + (2 + v) * GBM * GKP + row * GKP + lk) * 2;
                CPASYNC16(db, gB[v] + (size_t)(bcol + row) * K + k0 + lk);
            }
        }
    };

    load_stage(0, 0);
    asm volatile("cp.async.commit_group;");
    load_stage(1, GBK);
    asm volatile("cp.async.commit_group;");

    for (int kc = 0; kc < NK; kc++) {
        if (kc + 1 < NK) {
            asm volatile("cp.async.wait_group 1;");
        } else {
            asm volatile("cp.async.wait_group 0;");
        }
        __syncthreads();
        if (kc + 2 < NK) {
            load_stage((kc + 2) % NSTG, (kc + 2) * GBK);
            asm volatile("cp.async.commit_group;");
        }

        const int abase = (kc % NSTG) * GSTAGE;
#pragma unroll
        for (int ks = 0; ks < 2; ks++) {
            uint32_t aH[2][4], aL[2][4], bH[8][2], bL[8][2];
#pragma unroll
            for (int mt = 0; mt < 2; mt++) {
                uint32_t ad = sbase +
                    (uint32_t)(abase + (wm * 32 + mt * 16 + a_r) * GKP + ks * 16 + a_k) * 2;
                LDSM4(aH[mt][0], aH[mt][1], aH[mt][2], aH[mt][3], ad);
                ad += (uint32_t)(GBM * GKP) * 2;
                LDSM4(aL[mt][0], aL[mt][1], aL[mt][2], aL[mt][3], ad);
            }
#pragma unroll
            for (int p = 0; p < 4; p++) {
                uint32_t bd = sbase +
                    (uint32_t)(abase + 2 * GBM * GKP + (wn * 64 + p * 16 + b_r) * GKP + ks * 16 + b_k) * 2;
                LDSM4(bH[2 * p][0], bH[2 * p][1], bH[2 * p + 1][0], bH[2 * p + 1][1], bd);
                bd += (uint32_t)(GBM * GKP) * 2;
                LDSM4(bL[2 * p][0], bL[2 * p][1], bL[2 * p + 1][0], bL[2 * p + 1][1], bd);
            }
            // term-major: 16 independent MMAs between accumulator reuses
#pragma unroll
            for (int mt = 0; mt < 2; mt++)
#pragma unroll
                for (int nt = 0; nt < 8; nt++)
                    MMA16816(acc[mt][nt], aH[mt], bH[nt]);
#pragma unroll
            for (int mt = 0; mt < 2; mt++)
#pragma unroll
                for (int nt = 0; nt < 8; nt++)
                    MMA16816(acc[mt][nt], aH[mt], bL[nt]);
#pragma unroll
            for (int mt = 0; mt < 2; mt++)
#pragma unroll
                for (int nt = 0; nt < 8; nt++)
                    MMA16816(acc[mt][nt], aL[mt], bH[nt]);
        }
        __syncthreads();
    }

#pragma unroll
    for (int mt = 0; mt < 2; mt++) {
        int row0 = brow + wm * 32 + mt * 16 + (lane >> 2);
#pragma unroll
        for (int nt = 0; nt < 8; nt++) {
            int col = bcol + wn * 64 + nt * 8 + ((lane & 3) << 1);
            float b0 = bias[col], b1 = bias[col + 1];
            float v00 = acc[mt][nt][0] + b0, v01 = acc[mt][nt][1] + b1;
            float v10 = acc[mt][nt][2] + b0, v11 = acc[mt][nt][3] + b1;
            if (SPLIT_OUT) {
                uint32_t hi, lo;
                size_t o0 = ((size_t)row0 * N + col) >> 1;
                size_t o1 = ((size_t)(row0 + 8) * N + col) >> 1;
                split_pack(v00, v01, hi, lo);
                ((uint32_t*)Chi)[o0] = hi;
                ((uint32_t*)Clo)[o0] = lo;
                split_pack(v10, v11, hi, lo);
                ((uint32_t*)Chi)[o1] = hi;
                ((uint32_t*)Clo)[o1] = lo;
            } else {
                *(float2*)(C + (size_t)row0 * N + col) = make_float2(v00, v01);
                *(float2*)(C + (size_t)(row0 + 8) * N + col) = make_float2(v10, v11);
            }
        }
    }
}

// ---------------------------------------------------------------------------
// Tensor-core flash attention (bf16x3), term-major MMA ordering, no reg cap.
// ---------------------------------------------------------------------------
#define TQ 128
#define TK 64
#define PR 72
#define QELE (TQ * PR)
#define STG_ELE (4 * TK * PR)
#define ASMEM ((2 * QELE + 2 * STG_ELE) * 2)

__global__ __launch_bounds__(256, 1) void attn_tc(
    const __nv_bfloat16* __restrict__ qkvh,
    const __nv_bfloat16* __restrict__ qkvl,
    __nv_bfloat16* __restrict__ outh,
    __nv_bfloat16* __restrict__ outl)
{
    extern __shared__ __nv_bfloat16 as[];
    const int tid = threadIdx.x;
    const int lane = tid & 31, warp = tid >> 5;
    const int qt = blockIdx.x, h = blockIdx.y, b = blockIdx.z;

    uint32_t sbase = (uint32_t)__cvta_generic_to_shared(as);

    const int a_r = lane & 15;
    const int a_k = (lane >> 4) << 3;
    const int bg = lane >> 3;
    const int b_r = ((bg & 2) << 2) + (lane & 7);
    const int b_k = (bg & 1) << 3;
    const int tb_k = ((bg & 1) << 3) + (lane & 7);
    const int tb_n = (bg & 2) << 2;

    const size_t qrow0 = ((size_t)b * SEQ + (size_t)qt * TQ);

    {
        const __nv_bfloat16* src[2] = {qkvh, qkvl};
#pragma unroll
        for (int v = 0; v < 2; v++)
#pragma unroll
            for (int i = 0; i < 4; i++) {
                int c = i * 256 + tid;
                int row = c >> 3, col8 = (c & 7) << 3;
                uint32_t dst = sbase + (uint32_t)(v * QELE + row * PR + col8) * 2;
                CPASYNC16(dst, src[v] + (qrow0 + row) * QKV_COLS + h * DHEAD + col8);
            }
    }

    auto load_kv = [&](int st, int t) {
        const __nv_bfloat16* src[2] = {qkvh, qkvl};
        size_t krow0 = (size_t)b * SEQ + (size_t)t * TK;
#pragma unroll
        for (int m = 0; m < 4; m++) {
            int gofs = (m < 2 ? INNER : 2 * INNER) + h * DHEAD;
            const __nv_bfloat16* s = src[m & 1];
#pragma unroll
            for (int i = 0; i < 2; i++) {
                int c = i * 256 + tid;
                int row = c >> 3, col8 = (c & 7) << 3;
                uint32_t dst = sbase +
                    (uint32_t)(2 * QELE + st * STG_ELE + m * TK * PR + row * PR + col8) * 2;
                CPASYNC16(dst, s + (krow0 + row) * QKV_COLS + gofs + col8);
            }
        }
    };

    load_kv(0, 0);
    asm volatile("cp.async.commit_group;");

    float acc_o[8][4] = {};
    float mrow[2] = {-1e30f, -1e30f};
    float lrow[2] = {0.f, 0.f};

    const int NT = SEQ / TK;
    for (int t = 0; t < NT; t++) {
        if (t + 1 < NT) {
            load_kv((t + 1) & 1, t + 1);
            asm volatile("cp.async.commit_group;");
            asm volatile("cp.async.wait_group 1;");
        } else {
            asm volatile("cp.async.wait_group 0;");
        }
        __syncthreads();

        const int kb = 2 * QELE + (t & 1) * STG_ELE;

        // ---- S = Qh Kh + Qh Kl + Ql Kh  (term-major) ----
        float acc_s[8][4] = {};
#pragma unroll
        for (int ks = 0; ks < 4; ks++) {
            uint32_t aH[4], aL[4], bH[8][2], bL[8][2];
            uint32_t ad = sbase + (uint32_t)((warp * 16 + a_r) * PR + ks * 16 + a_k) * 2;
            LDSM4(aH[0], aH[1], aH[2], aH[3], ad);
            LDSM4(aL[0], aL[1], aL[2], aL[3], ad + (uint32_t)QELE * 2);
#pragma unroll
            for (int p = 0; p < 4; p++) {
                uint32_t bd = sbase +
                    (uint32_t)(kb + (p * 16 + b_r) * PR + ks * 16 + b_k) * 2;
                LDSM4(bH[2 * p][0], bH[2 * p][1], bH[2 * p + 1][0], bH[2 * p + 1][1], bd);
                LDSM4(bL[2 * p][0], bL[2 * p][1], bL[2 * p + 1][0], bL[2 * p + 1][1],
                      bd + (uint32_t)(TK * PR) * 2);
            }
#pragma unroll
            for (int nt = 0; nt < 8; nt++)
                MMAS(acc_s[nt], aH[0], aH[1], aH[2], aH[3], bH[nt][0], bH[nt][1]);
#pragma unroll
            for (int nt = 0; nt < 8; nt++)
                MMAS(acc_s[nt], aH[0], aH[1], aH[2], aH[3], bL[nt][0], bL[nt][1]);
#pragma unroll
            for (int nt = 0; nt < 8; nt++)
                MMAS(acc_s[nt], aL[0], aL[1], aL[2], aL[3], bH[nt][0], bH[nt][1]);
        }

        // ---- online softmax ----
#pragma unroll
        for (int nt = 0; nt < 8; nt++)
#pragma unroll
            for (int j = 0; j < 4; j++) acc_s[nt][j] *= ATT_SCALE;

#pragma unroll
        for (int r = 0; r < 2; r++) {
            float mx = -1e30f;
#pragma unroll
            for (int nt = 0; nt < 8; nt++)
                mx = fmaxf(mx, fmaxf(acc_s[nt][2 * r], acc_s[nt][2 * r + 1]));
            mx = fmaxf(mx, __shfl_xor_sync(0xffffffffu, mx, 1));
            mx = fmaxf(mx, __shfl_xor_sync(0xffffffffu, mx, 2));
            float mn = fmaxf(mrow[r], mx);
            float corr = __expf(mrow[r] - mn);
            mrow[r] = mn;
            float sum = 0.f;
#pragma unroll
            for (int nt = 0; nt < 8; nt++) {
                float p0 = __expf(acc_s[nt][2 * r] - mn);
                float p1 = __expf(acc_s[nt][2 * r + 1] - mn);
                acc_s[nt][2 * r] = p0;
                acc_s[nt][2 * r + 1] = p1;
                sum += p0 + p1;
            }
            sum += __shfl_xor_sync(0xffffffffu, sum, 1);
            sum += __shfl_xor_sync(0xffffffffu, sum, 2);
            lrow[r] = lrow[r] * corr + sum;
#pragma unroll
            for (int nt = 0; nt < 8; nt++) {
                acc_o[nt][2 * r] *= corr;
                acc_o[nt][2 * r + 1] *= corr;
            }
        }

        // ---- O += Ph Vh + Ph Vl + Pl Vh  (term-major) ----
        const int vb = kb + 2 * TK * PR;
#pragma unroll
        for (int kc = 0; kc < 4; kc++) {
            uint32_t aPh[4], aPl[4], vH[8][2], vL[8][2];
#pragma unroll
            for (int j = 0; j < 4; j++) {
                int tile = 2 * kc + (j >> 1);
                int c0 = (j & 1) << 1;
                split_pack(acc_s[tile][c0], acc_s[tile][c0 + 1], aPh[j], aPl[j]);
            }
#pragma unroll
            for (int p = 0; p < 4; p++) {
                uint32_t vd = sbase +
                    (uint32_t)(vb + (kc * 16 + tb_k) * PR + p * 16 + tb_n) * 2;
                LDSM4T(vH[2 * p][0], vH[2 * p][1], vH[2 * p + 1][0], vH[2 * p + 1][1], vd);
                LDSM4T(vL[2 * p][0], vL[2 * p][1], vL[2 * p + 1][0], vL[2 * p + 1][1],
                       vd + (uint32_t)(TK * PR) * 2);
            }
#pragma unroll
            for (int nt = 0; nt < 8; nt++)
                MMAS(acc_o[nt], aPh[0], aPh[1], aPh[2], aPh[3], vH[nt][0], vH[nt][1]);
#pragma unroll
            for (int nt = 0; nt < 8; nt++)
                MMAS(acc_o[nt], aPh[0], aPh[1], aPh[2], aPh[3], vL[nt][0], vL[nt][1]);
#pragma unroll
            for (int nt = 0; nt < 8; nt++)
                MMAS(acc_o[nt], aPl[0], aPl[1], aPl[2], aPl[3], vH[nt][0], vH[nt][1]);
        }
        __syncthreads();
    }

    float inv0 = 1.0f / lrow[0], inv1 = 1.0f / lrow[1];
    size_t row0 = qrow0 + warp * 16 + (lane >> 2);
#pragma unroll
    for (int nt = 0; nt < 8; nt++) {
        int col = h * DHEAD + nt * 8 + ((lane & 3) << 1);
        uint32_t hi, lo;
        size_t o0 = (row0 * INNER + col) >> 1;
        size_t o1 = ((row0 + 8) * INNER + col) >> 1;
        split_pack(acc_o[nt][0] * inv0, acc_o[nt][1] * inv0, hi, lo);
        ((uint32_t*)outh)[o0] = hi;
        ((uint32_t*)outl)[o0] = lo;
        split_pack(acc_o[nt][2] * inv1, acc_o[nt][3] * inv1, hi, lo);
        ((uint32_t*)outh)[o1] = hi;
        ((uint32_t*)outl)[o1] = lo;
    }
}

// ---------------------------------------------------------------------------
extern "C" void kernel_launch(void* const* d_in, const int* in_sizes, int n_in,
                              void* d_out, int out_size)
{
    const float* x     = (const float*)d_in[0];
    const float* w_qkv = (const float*)d_in[1];
    const float* b_qkv = (const float*)d_in[2];
    const float* w_out = (const float*)d_in[3];
    const float* b_out = (const float*)d_in[4];
    float* out = (float*)d_out;

    __nv_bfloat16 *xh, *xl, *qh, *ql, *oh, *ol, *wqh, *wql, *woh, *wol;
    cudaGetSymbolAddress((void**)&xh, g_xh);
    cudaGetSymbolAddress((void**)&xl, g_xl);
    cudaGetSymbolAddress((void**)&qh, g_qkvh);
    cudaGetSymbolAddress((void**)&ql, g_qkvl);
    cudaGetSymbolAddress((void**)&oh, g_oh);
    cudaGetSymbolAddress((void**)&ol, g_ol);
    cudaGetSymbolAddress((void**)&wqh, g_wqkvh);
    cudaGetSymbolAddress((void**)&wql, g_wqkvl);
    cudaGetSymbolAddress((void**)&woh, g_wouth);
    cudaGetSymbolAddress((void**)&wol, g_woutl);

    cudaFuncSetAttribute(gemm_bf16x3<true>,
                         cudaFuncAttributeMaxDynamicSharedMemorySize, GSMEM);
    cudaFuncSetAttribute(gemm_bf16x3<false>,
                         cudaFuncAttributeMaxDynamicSharedMemorySize, GSMEM);
    cudaFuncSetAttribute(attn_tc,
                         cudaFuncAttributeMaxDynamicSharedMemorySize, ASMEM);

    split_f32<<<(ROWS * DIM / 4 + 255) / 256, 256>>>(x, xh, xl, ROWS * DIM / 4);
    transpose_split<<<dim3(QKV_COLS / 32, DIM / 32), dim3(32, 8)>>>(w_qkv, wqh, wql, DIM, QKV_COLS);
    transpose_split<<<dim3(DIM / 32, INNER / 32), dim3(32, 8)>>>(w_out, woh, wol, INNER, DIM);

    gemm_bf16x3<true><<<dim3(QKV_COLS / GBN, ROWS / GBM), 256, GSMEM>>>(
        xh, xl, wqh, wql, b_qkv, nullptr, qh, ql, ROWS, QKV_COLS, DIM);

    attn_tc<<<dim3(SEQ / TQ, HEADS, BATCH), 256, ASMEM>>>(qh, ql, oh, ol);

    gemm_bf16x3<false><<<dim3(DIM / GBN, ROWS / GBM), 256, GSMEM>>>(
        oh, ol, woh, wol, b_out, out, nullptr, nullptr, ROWS, DIM, INNER);
}

// round 6
// speedup vs baseline: 3.4029x; 3.4029x over previous
#include <cuda_runtime.h>
#include <cuda_fp16.h>
#include <cstdint>

#define BATCH 4
#define SEQ 2048
#define DIM 1024
#define HEADS 16
#define DHEAD 64
#define INNER 1024
#define ROWS (BATCH * SEQ)      /* 8192 */
#define QKV_COLS (3 * INNER)    /* 3072 */
#define ATT_SCALE 0.125f

// ---------------- scratch (device globals) ----------------------------------
__device__ __half g_xf[(size_t)ROWS * DIM];
__device__ __half g_qkvf[(size_t)ROWS * QKV_COLS];
__device__ __half g_of[(size_t)ROWS * INNER];
__device__ __half g_wqkvf[(size_t)QKV_COLS * DIM];  // [N][K]
__device__ __half g_woutf[(size_t)DIM * INNER];     // [N][K]

// ---------------------------------------------------------------------------
__device__ __forceinline__ uint32_t pack_h2(float a, float b) {
    __half2 h = __floats2half2_rn(a, b);
    return *(uint32_t*)&h;
}

__global__ void cvt_f32_f16(const float* __restrict__ in,
                            __half* __restrict__ o, int n4)
{
    int i = blockIdx.x * blockDim.x + threadIdx.x;
    if (i >= n4) return;
    float4 v = ((const float4*)in)[i];
    ((uint2*)o)[i] = make_uint2(pack_h2(v.x, v.y), pack_h2(v.z, v.w));
}

// W[K][N] fp32 -> T[N][K] fp16, 32x32 tiles
__global__ void transpose_cvt(const float* __restrict__ W,
                              __half* __restrict__ T, int K, int N)
{
    __shared__ float t[32][33];
    int k0 = blockIdx.y * 32, n0 = blockIdx.x * 32;
    int tx = threadIdx.x, ty = threadIdx.y;
#pragma unroll
    for (int j = 0; j < 4; j++)
        t[ty + j * 8][tx] = W[(size_t)(k0 + ty + j * 8) * N + n0 + tx];
    __syncthreads();
#pragma unroll
    for (int j = 0; j < 4; j++) {
        float f = t[tx][ty + j * 8];
        T[(size_t)(n0 + ty + j * 8) * K + k0 + tx] = __float2half_rn(f);
    }
}

// ---------------------------------------------------------------------------
#define LDSM4(r0, r1, r2, r3, addr)                                          \
    asm volatile("ldmatrix.sync.aligned.m8n8.x4.shared.b16 {%0,%1,%2,%3}, [%4];" \
                 : "=r"(r0), "=r"(r1), "=r"(r2), "=r"(r3) : "r"(addr))
#define LDSM4T(r0, r1, r2, r3, addr)                                         \
    asm volatile("ldmatrix.sync.aligned.m8n8.x4.trans.shared.b16 {%0,%1,%2,%3}, [%4];" \
                 : "=r"(r0), "=r"(r1), "=r"(r2), "=r"(r3) : "r"(addr))
#define MMAS(d, a0, a1, a2, a3, b0, b1)                                      \
    asm volatile("mma.sync.aligned.m16n8k16.row.col.f32.f16.f16.f32 "        \
                 "{%0,%1,%2,%3},{%4,%5,%6,%7},{%8,%9},{%0,%1,%2,%3};"        \
                 : "+f"(d[0]), "+f"(d[1]), "+f"(d[2]), "+f"(d[3])            \
                 : "r"(a0), "r"(a1), "r"(a2), "r"(a3), "r"(b0), "r"(b1))
#define MMAA(d, a, b)                                                        \
    MMAS(d, (a)[0], (a)[1], (a)[2], (a)[3], (b)[0], (b)[1])
#define CPASYNC16(dst, src)                                                  \
    asm volatile("cp.async.cg.shared.global [%0], [%1], 16;" :: "r"(dst), "l"(src))

// ---------------------------------------------------------------------------
// fp16 HMMA GEMM: C[M,N] = A[M,K] @ B^T ([N][K]) + bias
// BM=BN=128, BK=32, 256 thr, warp tile 32x64, 2-stage cp.async.
// ---------------------------------------------------------------------------
#define GBM 128
#define GBN 128
#define GBK 32
#define GKP 40
#define GSTAGE (2 * GBM * GKP)   /* A,B fp16 elems per stage */
#define GSMEM (2 * GSTAGE * 2)   /* bytes, 2 stages = 40960 */

template <bool FP16_OUT>
__global__ __launch_bounds__(256, 1) void gemm_f16(
    const __half* __restrict__ A, const __half* __restrict__ B,
    const float* __restrict__ bias, float* __restrict__ C,
    __half* __restrict__ Ch, int M, int N, int K)
{
    extern __shared__ __half sm[];
    const int tid = threadIdx.x;
    const int lane = tid & 31, warp = tid >> 5;
    const int wm = warp >> 1, wn = warp & 1;
    const int brow = blockIdx.y * GBM, bcol = blockIdx.x * GBN;

    uint32_t sbase = (uint32_t)__cvta_generic_to_shared(sm);
    const int lrow = tid >> 2;
    const int lk = (tid & 3) << 3;

    float acc[2][8][4] = {};

    const int a_r = lane & 15;
    const int a_k = (lane >> 4) << 3;
    const int bg = lane >> 3;
    const int b_r = ((bg & 2) << 2) + (lane & 7);
    const int b_k = (bg & 1) << 3;
    const int NK = K / GBK;

    auto load_stage = [&](int st, int k0) {
        int base = st * GSTAGE;
#pragma unroll
        for (int i = 0; i < 2; i++) {
            int row = lrow + i * 64;
            uint32_t da = sbase + (uint32_t)(base + row * GKP + lk) * 2;
            CPASYNC16(da, A + (size_t)(brow + row) * K + k0 + lk);
            uint32_t db = sbase + (uint32_t)(base + GBM * GKP + row * GKP + lk) * 2;
            CPASYNC16(db, B + (size_t)(bcol + row) * K + k0 + lk);
        }
    };

    load_stage(0, 0);
    asm volatile("cp.async.commit_group;");

    for (int kc = 0; kc < NK; kc++) {
        if (kc + 1 < NK) {
            load_stage((kc + 1) & 1, (kc + 1) * GBK);
            asm volatile("cp.async.commit_group;");
            asm volatile("cp.async.wait_group 1;");
        } else {
            asm volatile("cp.async.wait_group 0;");
        }
        __syncthreads();

        const int abase = (kc & 1) * GSTAGE;
#pragma unroll
        for (int ks = 0; ks < 2; ks++) {
            uint32_t aH[2][4], bH[8][2];
#pragma unroll
            for (int mt = 0; mt < 2; mt++) {
                uint32_t ad = sbase +
                    (uint32_t)(abase + (wm * 32 + mt * 16 + a_r) * GKP + ks * 16 + a_k) * 2;
                LDSM4(aH[mt][0], aH[mt][1], aH[mt][2], aH[mt][3], ad);
            }
#pragma unroll
            for (int p = 0; p < 4; p++) {
                uint32_t bd = sbase +
                    (uint32_t)(abase + GBM * GKP + (wn * 64 + p * 16 + b_r) * GKP + ks * 16 + b_k) * 2;
                LDSM4(bH[2 * p][0], bH[2 * p][1], bH[2 * p + 1][0], bH[2 * p + 1][1], bd);
            }
#pragma unroll
            for (int mt = 0; mt < 2; mt++)
#pragma unroll
                for (int nt = 0; nt < 8; nt++)
                    MMAA(acc[mt][nt], aH[mt], bH[nt]);
        }
        __syncthreads();
    }

#pragma unroll
    for (int mt = 0; mt < 2; mt++) {
        int row0 = brow + wm * 32 + mt * 16 + (lane >> 2);
#pragma unroll
        for (int nt = 0; nt < 8; nt++) {
            int col = bcol + wn * 64 + nt * 8 + ((lane & 3) << 1);
            float b0 = bias[col], b1 = bias[col + 1];
            float v00 = acc[mt][nt][0] + b0, v01 = acc[mt][nt][1] + b1;
            float v10 = acc[mt][nt][2] + b0, v11 = acc[mt][nt][3] + b1;
            if (FP16_OUT) {
                ((uint32_t*)Ch)[((size_t)row0 * N + col) >> 1] = pack_h2(v00, v01);
                ((uint32_t*)Ch)[((size_t)(row0 + 8) * N + col) >> 1] = pack_h2(v10, v11);
            } else {
                *(float2*)(C + (size_t)row0 * N + col) = make_float2(v00, v01);
                *(float2*)(C + (size_t)(row0 + 8) * N + col) = make_float2(v10, v11);
            }
        }
    }
}

// ---------------------------------------------------------------------------
// fp16 flash attention: 128 q-rows/CTA, 64-key double-buffered KV tiles.
// 8 warps x 16 q-rows. S accum fp32, P packed fp16 in regs (FA2). Out fp16.
// ---------------------------------------------------------------------------
#define TQ 128
#define TK 64
#define PR 72
#define QELE (TQ * PR)              /* 9216 */
#define STG_ELE (2 * TK * PR)       /* K + V: 9216 */
#define ASMEM ((QELE + 2 * STG_ELE) * 2)  /* 55296 B */

__global__ __launch_bounds__(256, 2) void attn_f16(
    const __half* __restrict__ qkv, __half* __restrict__ outf)
{
    extern __shared__ __half as[];
    const int tid = threadIdx.x;
    const int lane = tid & 31, warp = tid >> 5;
    const int qt = blockIdx.x, h = blockIdx.y, b = blockIdx.z;

    uint32_t sbase = (uint32_t)__cvta_generic_to_shared(as);

    const int a_r = lane & 15;
    const int a_k = (lane >> 4) << 3;
    const int bg = lane >> 3;
    const int b_r = ((bg & 2) << 2) + (lane & 7);
    const int b_k = (bg & 1) << 3;
    const int tb_k = ((bg & 1) << 3) + (lane & 7);
    const int tb_n = (bg & 2) << 2;

    const size_t qrow0 = ((size_t)b * SEQ + (size_t)qt * TQ);

    // Q: 128 rows x 64 cols fp16
#pragma unroll
    for (int i = 0; i < 4; i++) {
        int c = i * 256 + tid;
        int row = c >> 3, col8 = (c & 7) << 3;
        uint32_t dst = sbase + (uint32_t)(row * PR + col8) * 2;
        CPASYNC16(dst, qkv + (qrow0 + row) * QKV_COLS + h * DHEAD + col8);
    }

    auto load_kv = [&](int st, int t) {
        size_t krow0 = (size_t)b * SEQ + (size_t)t * TK;
#pragma unroll
        for (int m = 0; m < 2; m++) {           // K, V
            int gofs = (m == 0 ? INNER : 2 * INNER) + h * DHEAD;
#pragma unroll
            for (int i = 0; i < 2; i++) {
                int c = i * 256 + tid;
                int row = c >> 3, col8 = (c & 7) << 3;
                uint32_t dst = sbase +
                    (uint32_t)(QELE + st * STG_ELE + m * TK * PR + row * PR + col8) * 2;
                CPASYNC16(dst, qkv + (krow0 + row) * QKV_COLS + gofs + col8);
            }
        }
    };

    load_kv(0, 0);
    asm volatile("cp.async.commit_group;");

    float acc_o[8][4] = {};
    float mrow[2] = {-1e30f, -1e30f};
    float lrow[2] = {0.f, 0.f};

    const int NT = SEQ / TK;
    for (int t = 0; t < NT; t++) {
        if (t + 1 < NT) {
            load_kv((t + 1) & 1, t + 1);
            asm volatile("cp.async.commit_group;");
            asm volatile("cp.async.wait_group 1;");
        } else {
            asm volatile("cp.async.wait_group 0;");
        }
        __syncthreads();

        const int kb = QELE + (t & 1) * STG_ELE;

        // ---- S = Q K^T ----
        float acc_s[8][4] = {};
#pragma unroll
        for (int ks = 0; ks < 4; ks++) {
            uint32_t aH[4], bH[8][2];
            uint32_t ad = sbase + (uint32_t)((warp * 16 + a_r) * PR + ks * 16 + a_k) * 2;
            LDSM4(aH[0], aH[1], aH[2], aH[3], ad);
#pragma unroll
            for (int p = 0; p < 4; p++) {
                uint32_t bd = sbase +
                    (uint32_t)(kb + (p * 16 + b_r) * PR + ks * 16 + b_k) * 2;
                LDSM4(bH[2 * p][0], bH[2 * p][1], bH[2 * p + 1][0], bH[2 * p + 1][1], bd);
            }
#pragma unroll
            for (int nt = 0; nt < 8; nt++)
                MMAA(acc_s[nt], aH, bH[nt]);
        }

        // ---- online softmax ----
#pragma unroll
        for (int nt = 0; nt < 8; nt++)
#pragma unroll
            for (int j = 0; j < 4; j++) acc_s[nt][j] *= ATT_SCALE;

#pragma unroll
        for (int r = 0; r < 2; r++) {
            float mx = -1e30f;
#pragma unroll
            for (int nt = 0; nt < 8; nt++)
                mx = fmaxf(mx, fmaxf(acc_s[nt][2 * r], acc_s[nt][2 * r + 1]));
            mx = fmaxf(mx, __shfl_xor_sync(0xffffffffu, mx, 1));
            mx = fmaxf(mx, __shfl_xor_sync(0xffffffffu, mx, 2));
            float mn = fmaxf(mrow[r], mx);
            float corr = __expf(mrow[r] - mn);
            mrow[r] = mn;
            float sum = 0.f;
#pragma unroll
            for (int nt = 0; nt < 8; nt++) {
                float p0 = __expf(acc_s[nt][2 * r] - mn);
                float p1 = __expf(acc_s[nt][2 * r + 1] - mn);
                acc_s[nt][2 * r] = p0;
                acc_s[nt][2 * r + 1] = p1;
                sum += p0 + p1;
            }
            sum += __shfl_xor_sync(0xffffffffu, sum, 1);
            sum += __shfl_xor_sync(0xffffffffu, sum, 2);
            lrow[r] = lrow[r] * corr + sum;
#pragma unroll
            for (int nt = 0; nt < 8; nt++) {
                acc_o[nt][2 * r] *= corr;
                acc_o[nt][2 * r + 1] *= corr;
            }
        }

        // ---- O += P @ V ----
        const int vb = kb + TK * PR;
#pragma unroll
        for (int kc = 0; kc < 4; kc++) {
            uint32_t aP[4], vH[8][2];
#pragma unroll
            for (int j = 0; j < 4; j++) {
                int tile = 2 * kc + (j >> 1);
                int c0 = (j & 1) << 1;
                aP[j] = pack_h2(acc_s[tile][c0], acc_s[tile][c0 + 1]);
            }
#pragma unroll
            for (int p = 0; p < 4; p++) {
                uint32_t vd = sbase +
                    (uint32_t)(vb + (kc * 16 + tb_k) * PR + p * 16 + tb_n) * 2;
                LDSM4T(vH[2 * p][0], vH[2 * p][1], vH[2 * p + 1][0], vH[2 * p + 1][1], vd);
            }
#pragma unroll
            for (int nt = 0; nt < 8; nt++)
                MMAA(acc_o[nt], aP, vH[nt]);
        }
        __syncthreads();
    }

    // ---- epilogue: normalize, fp16 out [b n (h d)] ----
    float inv0 = 1.0f / lrow[0], inv1 = 1.0f / lrow[1];
    size_t row0 = qrow0 + warp * 16 + (lane >> 2);
#pragma unroll
    for (int nt = 0; nt < 8; nt++) {
        int col = h * DHEAD + nt * 8 + ((lane & 3) << 1);
        ((uint32_t*)outf)[(row0 * INNER + col) >> 1] =
            pack_h2(acc_o[nt][0] * inv0, acc_o[nt][1] * inv0);
        ((uint32_t*)outf)[((row0 + 8) * INNER + col) >> 1] =
            pack_h2(acc_o[nt][2] * inv1, acc_o[nt][3] * inv1);
    }
}

// ---------------------------------------------------------------------------
extern "C" void kernel_launch(void* const* d_in, const int* in_sizes, int n_in,
                              void* d_out, int out_size)
{
    const float* x     = (const float*)d_in[0];
    const float* w_qkv = (const float*)d_in[1];
    const float* b_qkv = (const float*)d_in[2];
    const float* w_out = (const float*)d_in[3];
    const float* b_out = (const float*)d_in[4];
    float* out = (float*)d_out;

    __half *xf, *qf, *of, *wqf, *wof;
    cudaGetSymbolAddress((void**)&xf, g_xf);
    cudaGetSymbolAddress((void**)&qf, g_qkvf);
    cudaGetSymbolAddress((void**)&of, g_of);
    cudaGetSymbolAddress((void**)&wqf, g_wqkvf);
    cudaGetSymbolAddress((void**)&wof, g_woutf);

    cudaFuncSetAttribute(gemm_f16<true>,
                         cudaFuncAttributeMaxDynamicSharedMemorySize, GSMEM);
    cudaFuncSetAttribute(gemm_f16<false>,
                         cudaFuncAttributeMaxDynamicSharedMemorySize, GSMEM);
    cudaFuncSetAttribute(attn_f16,
                         cudaFuncAttributeMaxDynamicSharedMemorySize, ASMEM);

    // 0) conversions
    cvt_f32_f16<<<(ROWS * DIM / 4 + 255) / 256, 256>>>(x, xf, ROWS * DIM / 4);
    transpose_cvt<<<dim3(QKV_COLS / 32, DIM / 32), dim3(32, 8)>>>(w_qkv, wqf, DIM, QKV_COLS);
    transpose_cvt<<<dim3(DIM / 32, INNER / 32), dim3(32, 8)>>>(w_out, wof, INNER, DIM);

    // 1) qkv = x @ w_qkv + b_qkv  (fp16 out)
    gemm_f16<true><<<dim3(QKV_COLS / GBN, ROWS / GBM), 256, GSMEM>>>(
        xf, wqf, b_qkv, nullptr, qf, ROWS, QKV_COLS, DIM);

    // 2) flash attention (fp16) -> fp16 [b n (h d)]
    attn_f16<<<dim3(SEQ / TQ, HEADS, BATCH), 256, ASMEM>>>(qf, of);

    // 3) out = attn @ w_out + b_out  (fp32 out)
    gemm_f16<false><<<dim3(DIM / GBN, ROWS / GBM), 256, GSMEM>>>(
        of, wof, b_out, out, nullptr, ROWS, DIM, INNER);
}

// round 7
// speedup vs baseline: 4.2321x; 1.2437x over previous
#include <cuda_runtime.h>
#include <cuda_fp16.h>
#include <cstdint>

#define BATCH 4
#define SEQ 2048
#define DIM 1024
#define HEADS 16
#define DHEAD 64
#define INNER 1024
#define ROWS (BATCH * SEQ)      /* 8192 */
#define QKV_COLS (3 * INNER)    /* 3072 */
#define ATT_SCALE 0.125f

// ---------------- scratch (device globals) ----------------------------------
__device__ __half g_xf[(size_t)ROWS * DIM];
__device__ __half g_qkvf[(size_t)ROWS * QKV_COLS];
__device__ __half g_of[(size_t)ROWS * INNER];
__device__ __half g_wqkvf[(size_t)QKV_COLS * DIM];  // [N][K]
__device__ __half g_woutf[(size_t)DIM * INNER];     // [N][K]

// ---------------------------------------------------------------------------
__device__ __forceinline__ uint32_t pack_h2(float a, float b) {
    __half2 h = __floats2half2_rn(a, b);
    return *(uint32_t*)&h;
}

__global__ void cvt_f32_f16(const float* __restrict__ in,
                            __half* __restrict__ o, int n4)
{
    int i = blockIdx.x * blockDim.x + threadIdx.x;
    if (i >= n4) return;
    float4 v = ((const float4*)in)[i];
    ((uint2*)o)[i] = make_uint2(pack_h2(v.x, v.y), pack_h2(v.z, v.w));
}

// W[K][N] fp32 -> T[N][K] fp16, 32x32 tiles
__global__ void transpose_cvt(const float* __restrict__ W,
                              __half* __restrict__ T, int K, int N)
{
    __shared__ float t[32][33];
    int k0 = blockIdx.y * 32, n0 = blockIdx.x * 32;
    int tx = threadIdx.x, ty = threadIdx.y;
#pragma unroll
    for (int j = 0; j < 4; j++)
        t[ty + j * 8][tx] = W[(size_t)(k0 + ty + j * 8) * N + n0 + tx];
    __syncthreads();
#pragma unroll
    for (int j = 0; j < 4; j++) {
        float f = t[tx][ty + j * 8];
        T[(size_t)(n0 + ty + j * 8) * K + k0 + tx] = __float2half_rn(f);
    }
}

// ---------------------------------------------------------------------------
#define LDSM4(r0, r1, r2, r3, addr)                                          \
    asm volatile("ldmatrix.sync.aligned.m8n8.x4.shared.b16 {%0,%1,%2,%3}, [%4];" \
                 : "=r"(r0), "=r"(r1), "=r"(r2), "=r"(r3) : "r"(addr))
#define LDSM4T(r0, r1, r2, r3, addr)                                         \
    asm volatile("ldmatrix.sync.aligned.m8n8.x4.trans.shared.b16 {%0,%1,%2,%3}, [%4];" \
                 : "=r"(r0), "=r"(r1), "=r"(r2), "=r"(r3) : "r"(addr))
#define MMAS(d, a0, a1, a2, a3, b0, b1)                                      \
    asm volatile("mma.sync.aligned.m16n8k16.row.col.f32.f16.f16.f32 "        \
                 "{%0,%1,%2,%3},{%4,%5,%6,%7},{%8,%9},{%0,%1,%2,%3};"        \
                 : "+f"(d[0]), "+f"(d[1]), "+f"(d[2]), "+f"(d[3])            \
                 : "r"(a0), "r"(a1), "r"(a2), "r"(a3), "r"(b0), "r"(b1))
#define MMAA(d, a, b)                                                        \
    MMAS(d, (a)[0], (a)[1], (a)[2], (a)[3], (b)[0], (b)[1])
#define CPASYNC16(dst, src)                                                  \
    asm volatile("cp.async.cg.shared.global [%0], [%1], 16;" :: "r"(dst), "l"(src))

// ---------------------------------------------------------------------------
// fp16 HMMA GEMM: C[M,N] = A[M,K] @ B^T ([N][K]) + bias
// BM=BN=128, BK=64, 256 thr (8 warps, warp tile 32x64), 2-stage cp.async,
// B fragments streamed in halves to keep regs < 128 => 2 CTAs/SM.
// ---------------------------------------------------------------------------
#define GBM 128
#define GBN 128
#define GBK 64
#define GKP 72
#define GSTAGE (2 * GBM * GKP)   /* A,B fp16 elems per stage = 18432 */
#define GSMEM (2 * GSTAGE * 2)   /* 2 stages: 73728 bytes */

template <bool FP16_OUT>
__global__ __launch_bounds__(256, 2) void gemm_f16(
    const __half* __restrict__ A, const __half* __restrict__ B,
    const float* __restrict__ bias, float* __restrict__ C,
    __half* __restrict__ Ch, int M, int N, int K)
{
    extern __shared__ __half sm[];
    const int tid = threadIdx.x;
    const int lane = tid & 31, warp = tid >> 5;
    const int wm = warp >> 1, wn = warp & 1;
    const int brow = blockIdx.y * GBM, bcol = blockIdx.x * GBN;

    uint32_t sbase = (uint32_t)__cvta_generic_to_shared(sm);
    const int lrow = tid >> 3;           // 0..31
    const int lk = (tid & 7) << 3;       // 0..56

    float acc[2][8][4] = {};

    const int a_r = lane & 15;
    const int a_k = (lane >> 4) << 3;
    const int bg = lane >> 3;
    const int b_r = ((bg & 2) << 2) + (lane & 7);
    const int b_k = (bg & 1) << 3;
    const int NK = K / GBK;

    auto load_stage = [&](int st, int k0) {
        int base = st * GSTAGE;
#pragma unroll
        for (int i = 0; i < 4; i++) {
            int row = lrow + i * 32;
            uint32_t da = sbase + (uint32_t)(base + row * GKP + lk) * 2;
            CPASYNC16(da, A + (size_t)(brow + row) * K + k0 + lk);
            uint32_t db = sbase + (uint32_t)(base + GBM * GKP + row * GKP + lk) * 2;
            CPASYNC16(db, B + (size_t)(bcol + row) * K + k0 + lk);
        }
    };

    load_stage(0, 0);
    asm volatile("cp.async.commit_group;");

    for (int kc = 0; kc < NK; kc++) {
        if (kc + 1 < NK) {
            load_stage((kc + 1) & 1, (kc + 1) * GBK);
            asm volatile("cp.async.commit_group;");
            asm volatile("cp.async.wait_group 1;");
        } else {
            asm volatile("cp.async.wait_group 0;");
        }
        __syncthreads();

        const int abase = (kc & 1) * GSTAGE;
#pragma unroll
        for (int ks = 0; ks < 4; ks++) {
            uint32_t aH[2][4];
#pragma unroll
            for (int mt = 0; mt < 2; mt++) {
                uint32_t ad = sbase +
                    (uint32_t)(abase + (wm * 32 + mt * 16 + a_r) * GKP + ks * 16 + a_k) * 2;
                LDSM4(aH[mt][0], aH[mt][1], aH[mt][2], aH[mt][3], ad);
            }
#pragma unroll
            for (int half = 0; half < 2; half++) {
                uint32_t bH[4][2];
#pragma unroll
                for (int p = 0; p < 2; p++) {
                    uint32_t bd = sbase +
                        (uint32_t)(abase + GBM * GKP +
                                   (wn * 64 + half * 32 + p * 16 + b_r) * GKP +
                                   ks * 16 + b_k) * 2;
                    LDSM4(bH[2 * p][0], bH[2 * p][1], bH[2 * p + 1][0], bH[2 * p + 1][1], bd);
                }
#pragma unroll
                for (int mt = 0; mt < 2; mt++)
#pragma unroll
                    for (int j = 0; j < 4; j++)
                        MMAA(acc[mt][half * 4 + j], aH[mt], bH[j]);
            }
        }
        __syncthreads();
    }

#pragma unroll
    for (int mt = 0; mt < 2; mt++) {
        int row0 = brow + wm * 32 + mt * 16 + (lane >> 2);
#pragma unroll
        for (int nt = 0; nt < 8; nt++) {
            int col = bcol + wn * 64 + nt * 8 + ((lane & 3) << 1);
            float b0 = bias[col], b1 = bias[col + 1];
            float v00 = acc[mt][nt][0] + b0, v01 = acc[mt][nt][1] + b1;
            float v10 = acc[mt][nt][2] + b0, v11 = acc[mt][nt][3] + b1;
            if (FP16_OUT) {
                ((uint32_t*)Ch)[((size_t)row0 * N + col) >> 1] = pack_h2(v00, v01);
                ((uint32_t*)Ch)[((size_t)(row0 + 8) * N + col) >> 1] = pack_h2(v10, v11);
            } else {
                *(float2*)(C + (size_t)row0 * N + col) = make_float2(v00, v01);
                *(float2*)(C + (size_t)(row0 + 8) * N + col) = make_float2(v10, v11);
            }
        }
    }
}

// ---------------------------------------------------------------------------
// fp16 flash attention: 128 q-rows/CTA, 64-key double-buffered KV tiles.
// 8 warps x 16 q-rows. S accum fp32, P packed fp16 in regs (FA2). Out fp16.
// ---------------------------------------------------------------------------
#define TQ 128
#define TK 64
#define PR 72
#define QELE (TQ * PR)              /* 9216 */
#define STG_ELE (2 * TK * PR)       /* K + V: 9216 */
#define ASMEM ((QELE + 2 * STG_ELE) * 2)  /* 55296 B */

__global__ __launch_bounds__(256, 2) void attn_f16(
    const __half* __restrict__ qkv, __half* __restrict__ outf)
{
    extern __shared__ __half as[];
    const int tid = threadIdx.x;
    const int lane = tid & 31, warp = tid >> 5;
    const int qt = blockIdx.x, h = blockIdx.y, b = blockIdx.z;

    uint32_t sbase = (uint32_t)__cvta_generic_to_shared(as);

    const int a_r = lane & 15;
    const int a_k = (lane >> 4) << 3;
    const int bg = lane >> 3;
    const int b_r = ((bg & 2) << 2) + (lane & 7);
    const int b_k = (bg & 1) << 3;
    const int tb_k = ((bg & 1) << 3) + (lane & 7);
    const int tb_n = (bg & 2) << 2;

    const size_t qrow0 = ((size_t)b * SEQ + (size_t)qt * TQ);

    // Q: 128 rows x 64 cols fp16
#pragma unroll
    for (int i = 0; i < 4; i++) {
        int c = i * 256 + tid;
        int row = c >> 3, col8 = (c & 7) << 3;
        uint32_t dst = sbase + (uint32_t)(row * PR + col8) * 2;
        CPASYNC16(dst, qkv + (qrow0 + row) * QKV_COLS + h * DHEAD + col8);
    }

    auto load_kv = [&](int st, int t) {
        size_t krow0 = (size_t)b * SEQ + (size_t)t * TK;
#pragma unroll
        for (int m = 0; m < 2; m++) {           // K, V
            int gofs = (m == 0 ? INNER : 2 * INNER) + h * DHEAD;
#pragma unroll
            for (int i = 0; i < 2; i++) {
                int c = i * 256 + tid;
                int row = c >> 3, col8 = (c & 7) << 3;
                uint32_t dst = sbase +
                    (uint32_t)(QELE + st * STG_ELE + m * TK * PR + row * PR + col8) * 2;
                CPASYNC16(dst, qkv + (krow0 + row) * QKV_COLS + gofs + col8);
            }
        }
    };

    load_kv(0, 0);
    asm volatile("cp.async.commit_group;");

    float acc_o[8][4] = {};
    float mrow[2] = {-1e30f, -1e30f};
    float lrow[2] = {0.f, 0.f};

    const int NT = SEQ / TK;
    for (int t = 0; t < NT; t++) {
        if (t + 1 < NT) {
            load_kv((t + 1) & 1, t + 1);
            asm volatile("cp.async.commit_group;");
            asm volatile("cp.async.wait_group 1;");
        } else {
            asm volatile("cp.async.wait_group 0;");
        }
        __syncthreads();

        const int kb = QELE + (t & 1) * STG_ELE;

        // ---- S = Q K^T ----
        float acc_s[8][4] = {};
#pragma unroll
        for (int ks = 0; ks < 4; ks++) {
            uint32_t aH[4], bH[8][2];
            uint32_t ad = sbase + (uint32_t)((warp * 16 + a_r) * PR + ks * 16 + a_k) * 2;
            LDSM4(aH[0], aH[1], aH[2], aH[3], ad);
#pragma unroll
            for (int p = 0; p < 4; p++) {
                uint32_t bd = sbase +
                    (uint32_t)(kb + (p * 16 + b_r) * PR + ks * 16 + b_k) * 2;
                LDSM4(bH[2 * p][0], bH[2 * p][1], bH[2 * p + 1][0], bH[2 * p + 1][1], bd);
            }
#pragma unroll
            for (int nt = 0; nt < 8; nt++)
                MMAA(acc_s[nt], aH, bH[nt]);
        }

        // ---- online softmax ----
#pragma unroll
        for (int nt = 0; nt < 8; nt++)
#pragma unroll
            for (int j = 0; j < 4; j++) acc_s[nt][j] *= ATT_SCALE;

#pragma unroll
        for (int r = 0; r < 2; r++) {
            float mx = -1e30f;
#pragma unroll
            for (int nt = 0; nt < 8; nt++)
                mx = fmaxf(mx, fmaxf(acc_s[nt][2 * r], acc_s[nt][2 * r + 1]));
            mx = fmaxf(mx, __shfl_xor_sync(0xffffffffu, mx, 1));
            mx = fmaxf(mx, __shfl_xor_sync(0xffffffffu, mx, 2));
            float mn = fmaxf(mrow[r], mx);
            float corr = __expf(mrow[r] - mn);
            mrow[r] = mn;
            float sum = 0.f;
#pragma unroll
            for (int nt = 0; nt < 8; nt++) {
                float p0 = __expf(acc_s[nt][2 * r] - mn);
                float p1 = __expf(acc_s[nt][2 * r + 1] - mn);
                acc_s[nt][2 * r] = p0;
                acc_s[nt][2 * r + 1] = p1;
                sum += p0 + p1;
            }
            sum += __shfl_xor_sync(0xffffffffu, sum, 1);
            sum += __shfl_xor_sync(0xffffffffu, sum, 2);
            lrow[r] = lrow[r] * corr + sum;
#pragma unroll
            for (int nt = 0; nt < 8; nt++) {
                acc_o[nt][2 * r] *= corr;
                acc_o[nt][2 * r + 1] *= corr;
            }
        }

        // ---- O += P @ V ----
        const int vb = kb + TK * PR;
#pragma unroll
        for (int kc = 0; kc < 4; kc++) {
            uint32_t aP[4], vH[8][2];
#pragma unroll
            for (int j = 0; j < 4; j++) {
                int tile = 2 * kc + (j >> 1);
                int c0 = (j & 1) << 1;
                aP[j] = pack_h2(acc_s[tile][c0], acc_s[tile][c0 + 1]);
            }
#pragma unroll
            for (int p = 0; p < 4; p++) {
                uint32_t vd = sbase +
                    (uint32_t)(vb + (kc * 16 + tb_k) * PR + p * 16 + tb_n) * 2;
                LDSM4T(vH[2 * p][0], vH[2 * p][1], vH[2 * p + 1][0], vH[2 * p + 1][1], vd);
            }
#pragma unroll
            for (int nt = 0; nt < 8; nt++)
                MMAA(acc_o[nt], aP, vH[nt]);
        }
        __syncthreads();
    }

    // ---- epilogue: normalize, fp16 out [b n (h d)] ----
    float inv0 = 1.0f / lrow[0], inv1 = 1.0f / lrow[1];
    size_t row0 = qrow0 + warp * 16 + (lane >> 2);
#pragma unroll
    for (int nt = 0; nt < 8; nt++) {
        int col = h * DHEAD + nt * 8 + ((lane & 3) << 1);
        ((uint32_t*)outf)[(row0 * INNER + col) >> 1] =
            pack_h2(acc_o[nt][0] * inv0, acc_o[nt][1] * inv0);
        ((uint32_t*)outf)[((row0 + 8) * INNER + col) >> 1] =
            pack_h2(acc_o[nt][2] * inv1, acc_o[nt][3] * inv1);
    }
}

// ---------------------------------------------------------------------------
extern "C" void kernel_launch(void* const* d_in, const int* in_sizes, int n_in,
                              void* d_out, int out_size)
{
    const float* x     = (const float*)d_in[0];
    const float* w_qkv = (const float*)d_in[1];
    const float* b_qkv = (const float*)d_in[2];
    const float* w_out = (const float*)d_in[3];
    const float* b_out = (const float*)d_in[4];
    float* out = (float*)d_out;

    __half *xf, *qf, *of, *wqf, *wof;
    cudaGetSymbolAddress((void**)&xf, g_xf);
    cudaGetSymbolAddress((void**)&qf, g_qkvf);
    cudaGetSymbolAddress((void**)&of, g_of);
    cudaGetSymbolAddress((void**)&wqf, g_wqkvf);
    cudaGetSymbolAddress((void**)&wof, g_woutf);

    cudaFuncSetAttribute(gemm_f16<true>,
                         cudaFuncAttributeMaxDynamicSharedMemorySize, GSMEM);
    cudaFuncSetAttribute(gemm_f16<false>,
                         cudaFuncAttributeMaxDynamicSharedMemorySize, GSMEM);
    cudaFuncSetAttribute(attn_f16,
                         cudaFuncAttributeMaxDynamicSharedMemorySize, ASMEM);

    // 0) conversions
    cvt_f32_f16<<<(ROWS * DIM / 4 + 255) / 256, 256>>>(x, xf, ROWS * DIM / 4);
    transpose_cvt<<<dim3(QKV_COLS / 32, DIM / 32), dim3(32, 8)>>>(w_qkv, wqf, DIM, QKV_COLS);
    transpose_cvt<<<dim3(DIM / 32, INNER / 32), dim3(32, 8)>>>(w_out, wof, INNER, DIM);

    // 1) qkv = x @ w_qkv + b_qkv  (fp16 out)
    gemm_f16<true><<<dim3(QKV_COLS / GBN, ROWS / GBM), 256, GSMEM>>>(
        xf, wqf, b_qkv, nullptr, qf, ROWS, QKV_COLS, DIM);

    // 2) flash attention (fp16) -> fp16 [b n (h d)]
    attn_f16<<<dim3(SEQ / TQ, HEADS, BATCH), 256, ASMEM>>>(qf, of);

    // 3) out = attn @ w_out + b_out  (fp32 out)
    gemm_f16<false><<<dim3(DIM / GBN, ROWS / GBM), 256, GSMEM>>>(
        of, wof, b_out, out, nullptr, ROWS, DIM, INNER);
}

// round 8
// speedup vs baseline: 4.2690x; 1.0087x over previous
#include <cuda_runtime.h>
#include <cuda_fp16.h>
#include <cstdint>

#define BATCH 4
#define SEQ 2048
#define DIM 1024
#define HEADS 16
#define DHEAD 64
#define INNER 1024
#define ROWS (BATCH * SEQ)      /* 8192 */
#define QKV_COLS (3 * INNER)    /* 3072 */
#define ATT_SCALE 0.125f

// ---------------- scratch (device globals) ----------------------------------
__device__ __half g_xf[(size_t)ROWS * DIM];
__device__ __half g_qkvf[(size_t)ROWS * QKV_COLS];
__device__ __half g_of[(size_t)ROWS * INNER];
__device__ __half g_wqkvf[(size_t)QKV_COLS * DIM];  // [N][K]
__device__ __half g_woutf[(size_t)DIM * INNER];     // [N][K]

// ---------------------------------------------------------------------------
__device__ __forceinline__ uint32_t pack_h2(float a, float b) {
    __half2 h = __floats2half2_rn(a, b);
    return *(uint32_t*)&h;
}

__global__ void cvt_f32_f16(const float* __restrict__ in,
                            __half* __restrict__ o, int n4)
{
    int i = blockIdx.x * blockDim.x + threadIdx.x;
    if (i >= n4) return;
    float4 v = ((const float4*)in)[i];
    ((uint2*)o)[i] = make_uint2(pack_h2(v.x, v.y), pack_h2(v.z, v.w));
}

// W[K][N] fp32 -> T[N][K] fp16, 32x32 tiles
__global__ void transpose_cvt(const float* __restrict__ W,
                              __half* __restrict__ T, int K, int N)
{
    __shared__ float t[32][33];
    int k0 = blockIdx.y * 32, n0 = blockIdx.x * 32;
    int tx = threadIdx.x, ty = threadIdx.y;
#pragma unroll
    for (int j = 0; j < 4; j++)
        t[ty + j * 8][tx] = W[(size_t)(k0 + ty + j * 8) * N + n0 + tx];
    __syncthreads();
#pragma unroll
    for (int j = 0; j < 4; j++) {
        float f = t[tx][ty + j * 8];
        T[(size_t)(n0 + ty + j * 8) * K + k0 + tx] = __float2half_rn(f);
    }
}

// ---------------------------------------------------------------------------
#define LDSM4(r0, r1, r2, r3, addr)                                          \
    asm volatile("ldmatrix.sync.aligned.m8n8.x4.shared.b16 {%0,%1,%2,%3}, [%4];" \
                 : "=r"(r0), "=r"(r1), "=r"(r2), "=r"(r3) : "r"(addr))
#define LDSM4T(r0, r1, r2, r3, addr)                                         \
    asm volatile("ldmatrix.sync.aligned.m8n8.x4.trans.shared.b16 {%0,%1,%2,%3}, [%4];" \
                 : "=r"(r0), "=r"(r1), "=r"(r2), "=r"(r3) : "r"(addr))
#define MMAS(d, a0, a1, a2, a3, b0, b1)                                      \
    asm volatile("mma.sync.aligned.m16n8k16.row.col.f32.f16.f16.f32 "        \
                 "{%0,%1,%2,%3},{%4,%5,%6,%7},{%8,%9},{%0,%1,%2,%3};"        \
                 : "+f"(d[0]), "+f"(d[1]), "+f"(d[2]), "+f"(d[3])            \
                 : "r"(a0), "r"(a1), "r"(a2), "r"(a3), "r"(b0), "r"(b1))
#define MMAA(d, a, b)                                                        \
    MMAS(d, (a)[0], (a)[1], (a)[2], (a)[3], (b)[0], (b)[1])
#define CPASYNC16(dst, src)                                                  \
    asm volatile("cp.async.cg.shared.global [%0], [%1], 16;" :: "r"(dst), "l"(src))

// ---------------------------------------------------------------------------
// fp16 HMMA GEMM: C[M,N] = A[M,K] @ B^T ([N][K]) + bias
// BM=BN=128, BK=64, 8 warps (warp tile 32x64), 3-stage cp.async ring,
// ONE __syncthreads per k-chunk. B fragments streamed in halves (regs<=128).
// ---------------------------------------------------------------------------
#define GBM 128
#define GBN 128
#define GBK 64
#define GKP 72
#define GSTAGE (2 * GBM * GKP)   /* A,B fp16 elems per stage = 18432 */
#define GNSTG 3
#define GSMEM (GNSTG * GSTAGE * 2)   /* 110592 bytes */

template <bool FP16_OUT>
__global__ __launch_bounds__(256, 2) void gemm_f16(
    const __half* __restrict__ A, const __half* __restrict__ B,
    const float* __restrict__ bias, float* __restrict__ C,
    __half* __restrict__ Ch, int M, int N, int K)
{
    extern __shared__ __half sm[];
    const int tid = threadIdx.x;
    const int lane = tid & 31, warp = tid >> 5;
    const int wm = warp >> 1, wn = warp & 1;
    const int brow = blockIdx.y * GBM, bcol = blockIdx.x * GBN;

    uint32_t sbase = (uint32_t)__cvta_generic_to_shared(sm);
    const int lrow = tid >> 3;           // 0..31
    const int lk = (tid & 7) << 3;       // 0..56

    float acc[2][8][4] = {};

    const int a_r = lane & 15;
    const int a_k = (lane >> 4) << 3;
    const int bg = lane >> 3;
    const int b_r = ((bg & 2) << 2) + (lane & 7);
    const int b_k = (bg & 1) << 3;
    const int NK = K / GBK;

    auto load_stage = [&](int st, int k0) {
        int base = st * GSTAGE;
#pragma unroll
        for (int i = 0; i < 4; i++) {
            int row = lrow + i * 32;
            uint32_t da = sbase + (uint32_t)(base + row * GKP + lk) * 2;
            CPASYNC16(da, A + (size_t)(brow + row) * K + k0 + lk);
            uint32_t db = sbase + (uint32_t)(base + GBM * GKP + row * GKP + lk) * 2;
            CPASYNC16(db, B + (size_t)(bcol + row) * K + k0 + lk);
        }
        asm volatile("cp.async.commit_group;");
    };

    load_stage(0, 0);
    load_stage(1, GBK);

    for (int kc = 0; kc < NK; kc++) {
        if (kc + 1 < NK) {
            asm volatile("cp.async.wait_group 1;");
        } else {
            asm volatile("cp.async.wait_group 0;");
        }
        __syncthreads();   // stage kc ready; everyone done reading stage kc-1

        if (kc + 2 < NK)
            load_stage((kc + 2) % GNSTG, (kc + 2) * GBK);

        const int abase = (kc % GNSTG) * GSTAGE;
#pragma unroll
        for (int ks = 0; ks < 4; ks++) {
            uint32_t aH[2][4];
#pragma unroll
            for (int mt = 0; mt < 2; mt++) {
                uint32_t ad = sbase +
                    (uint32_t)(abase + (wm * 32 + mt * 16 + a_r) * GKP + ks * 16 + a_k) * 2;
                LDSM4(aH[mt][0], aH[mt][1], aH[mt][2], aH[mt][3], ad);
            }
#pragma unroll
            for (int half = 0; half < 2; half++) {
                uint32_t bH[4][2];
#pragma unroll
                for (int p = 0; p < 2; p++) {
                    uint32_t bd = sbase +
                        (uint32_t)(abase + GBM * GKP +
                                   (wn * 64 + half * 32 + p * 16 + b_r) * GKP +
                                   ks * 16 + b_k) * 2;
                    LDSM4(bH[2 * p][0], bH[2 * p][1], bH[2 * p + 1][0], bH[2 * p + 1][1], bd);
                }
#pragma unroll
                for (int mt = 0; mt < 2; mt++)
#pragma unroll
                    for (int j = 0; j < 4; j++)
                        MMAA(acc[mt][half * 4 + j], aH[mt], bH[j]);
            }
        }
        // no trailing sync: next iteration's top sync protects stage reuse
    }

#pragma unroll
    for (int mt = 0; mt < 2; mt++) {
        int row0 = brow + wm * 32 + mt * 16 + (lane >> 2);
#pragma unroll
        for (int nt = 0; nt < 8; nt++) {
            int col = bcol + wn * 64 + nt * 8 + ((lane & 3) << 1);
            float b0 = bias[col], b1 = bias[col + 1];
            float v00 = acc[mt][nt][0] + b0, v01 = acc[mt][nt][1] + b1;
            float v10 = acc[mt][nt][2] + b0, v11 = acc[mt][nt][3] + b1;
            if (FP16_OUT) {
                ((uint32_t*)Ch)[((size_t)row0 * N + col) >> 1] = pack_h2(v00, v01);
                ((uint32_t*)Ch)[((size_t)(row0 + 8) * N + col) >> 1] = pack_h2(v10, v11);
            } else {
                *(float2*)(C + (size_t)row0 * N + col) = make_float2(v00, v01);
                *(float2*)(C + (size_t)(row0 + 8) * N + col) = make_float2(v10, v11);
            }
        }
    }
}

// ---------------------------------------------------------------------------
// fp16 flash attention: 128 q-rows/CTA, 64-key KV tiles, 3-stage ring,
// ONE __syncthreads per tile. S accum fp32, P packed fp16 in regs (FA2).
// ---------------------------------------------------------------------------
#define TQ 128
#define TK 64
#define PR 72
#define QELE (TQ * PR)              /* 9216 */
#define STG_ELE (2 * TK * PR)       /* K + V: 9216 */
#define ANSTG 3
#define ASMEM ((QELE + ANSTG * STG_ELE) * 2)  /* 73728 B */

__global__ __launch_bounds__(256, 2) void attn_f16(
    const __half* __restrict__ qkv, __half* __restrict__ outf)
{
    extern __shared__ __half as[];
    const int tid = threadIdx.x;
    const int lane = tid & 31, warp = tid >> 5;
    const int qt = blockIdx.x, h = blockIdx.y, b = blockIdx.z;

    uint32_t sbase = (uint32_t)__cvta_generic_to_shared(as);

    const int a_r = lane & 15;
    const int a_k = (lane >> 4) << 3;
    const int bg = lane >> 3;
    const int b_r = ((bg & 2) << 2) + (lane & 7);
    const int b_k = (bg & 1) << 3;
    const int tb_k = ((bg & 1) << 3) + (lane & 7);
    const int tb_n = (bg & 2) << 2;

    const size_t qrow0 = ((size_t)b * SEQ + (size_t)qt * TQ);

    auto load_kv = [&](int st, int t) {
        size_t krow0 = (size_t)b * SEQ + (size_t)t * TK;
#pragma unroll
        for (int m = 0; m < 2; m++) {           // K, V
            int gofs = (m == 0 ? INNER : 2 * INNER) + h * DHEAD;
#pragma unroll
            for (int i = 0; i < 2; i++) {
                int c = i * 256 + tid;
                int row = c >> 3, col8 = (c & 7) << 3;
                uint32_t dst = sbase +
                    (uint32_t)(QELE + st * STG_ELE + m * TK * PR + row * PR + col8) * 2;
                CPASYNC16(dst, qkv + (krow0 + row) * QKV_COLS + gofs + col8);
            }
        }
        asm volatile("cp.async.commit_group;");
    };

    // group 0: Q + KV tile 0; group 1: KV tile 1
    {
#pragma unroll
        for (int i = 0; i < 4; i++) {
            int c = i * 256 + tid;
            int row = c >> 3, col8 = (c & 7) << 3;
            uint32_t dst = sbase + (uint32_t)(row * PR + col8) * 2;
            CPASYNC16(dst, qkv + (qrow0 + row) * QKV_COLS + h * DHEAD + col8);
        }
    }
    load_kv(0, 0);           // commits Q + kv0 together
    load_kv(1, 1);

    float acc_o[8][4] = {};
    float mrow[2] = {-1e30f, -1e30f};
    float lrow[2] = {0.f, 0.f};

    const int NT = SEQ / TK;
    for (int t = 0; t < NT; t++) {
        if (t + 1 < NT) {
            asm volatile("cp.async.wait_group 1;");
        } else {
            asm volatile("cp.async.wait_group 0;");
        }
        __syncthreads();   // stage t ready; all reads of stage t-1 complete

        if (t + 2 < NT)
            load_kv((t + 2) % ANSTG, t + 2);

        const int kb = QELE + (t % ANSTG) * STG_ELE;

        // ---- S = Q K^T ----
        float acc_s[8][4] = {};
#pragma unroll
        for (int ks = 0; ks < 4; ks++) {
            uint32_t aH[4], bH[8][2];
            uint32_t ad = sbase + (uint32_t)((warp * 16 + a_r) * PR + ks * 16 + a_k) * 2;
            LDSM4(aH[0], aH[1], aH[2], aH[3], ad);
#pragma unroll
            for (int p = 0; p < 4; p++) {
                uint32_t bd = sbase +
                    (uint32_t)(kb + (p * 16 + b_r) * PR + ks * 16 + b_k) * 2;
                LDSM4(bH[2 * p][0], bH[2 * p][1], bH[2 * p + 1][0], bH[2 * p + 1][1], bd);
            }
#pragma unroll
            for (int nt = 0; nt < 8; nt++)
                MMAA(acc_s[nt], aH, bH[nt]);
        }

        // ---- online softmax ----
#pragma unroll
        for (int nt = 0; nt < 8; nt++)
#pragma unroll
            for (int j = 0; j < 4; j++) acc_s[nt][j] *= ATT_SCALE;

#pragma unroll
        for (int r = 0; r < 2; r++) {
            float mx = -1e30f;
#pragma unroll
            for (int nt = 0; nt < 8; nt++)
                mx = fmaxf(mx, fmaxf(acc_s[nt][2 * r], acc_s[nt][2 * r + 1]));
            mx = fmaxf(mx, __shfl_xor_sync(0xffffffffu, mx, 1));
            mx = fmaxf(mx, __shfl_xor_sync(0xffffffffu, mx, 2));
            float mn = fmaxf(mrow[r], mx);
            float corr = __expf(mrow[r] - mn);
            mrow[r] = mn;
            float sum = 0.f;
#pragma unroll
            for (int nt = 0; nt < 8; nt++) {
                float p0 = __expf(acc_s[nt][2 * r] - mn);
                float p1 = __expf(acc_s[nt][2 * r + 1] - mn);
                acc_s[nt][2 * r] = p0;
                acc_s[nt][2 * r + 1] = p1;
                sum += p0 + p1;
            }
            sum += __shfl_xor_sync(0xffffffffu, sum, 1);
            sum += __shfl_xor_sync(0xffffffffu, sum, 2);
            lrow[r] = lrow[r] * corr + sum;
#pragma unroll
            for (int nt = 0; nt < 8; nt++) {
                acc_o[nt][2 * r] *= corr;
                acc_o[nt][2 * r + 1] *= corr;
            }
        }

        // ---- O += P @ V ----
        const int vb = kb + TK * PR;
#pragma unroll
        for (int kc = 0; kc < 4; kc++) {
            uint32_t aP[4], vH[8][2];
#pragma unroll
            for (int j = 0; j < 4; j++) {
                int tile = 2 * kc + (j >> 1);
                int c0 = (j & 1) << 1;
                aP[j] = pack_h2(acc_s[tile][c0], acc_s[tile][c0 + 1]);
            }
#pragma unroll
            for (int p = 0; p < 4; p++) {
                uint32_t vd = sbase +
                    (uint32_t)(vb + (kc * 16 + tb_k) * PR + p * 16 + tb_n) * 2;
                LDSM4T(vH[2 * p][0], vH[2 * p][1], vH[2 * p + 1][0], vH[2 * p + 1][1], vd);
            }
#pragma unroll
            for (int nt = 0; nt < 8; nt++)
                MMAA(acc_o[nt], aP, vH[nt]);
        }
        // no trailing sync (top-of-loop sync protects stage reuse)
    }

    // ---- epilogue: normalize, fp16 out [b n (h d)] ----
    float inv0 = 1.0f / lrow[0], inv1 = 1.0f / lrow[1];
    size_t row0 = qrow0 + warp * 16 + (lane >> 2);
#pragma unroll
    for (int nt = 0; nt < 8; nt++) {
        int col = h * DHEAD + nt * 8 + ((lane & 3) << 1);
        ((uint32_t*)outf)[(row0 * INNER + col) >> 1] =
            pack_h2(acc_o[nt][0] * inv0, acc_o[nt][1] * inv0);
        ((uint32_t*)outf)[((row0 + 8) * INNER + col) >> 1] =
            pack_h2(acc_o[nt][2] * inv1, acc_o[nt][3] * inv1);
    }
}

// ---------------------------------------------------------------------------
extern "C" void kernel_launch(void* const* d_in, const int* in_sizes, int n_in,
                              void* d_out, int out_size)
{
    const float* x     = (const float*)d_in[0];
    const float* w_qkv = (const float*)d_in[1];
    const float* b_qkv = (const float*)d_in[2];
    const float* w_out = (const float*)d_in[3];
    const float* b_out = (const float*)d_in[4];
    float* out = (float*)d_out;

    __half *xf, *qf, *of, *wqf, *wof;
    cudaGetSymbolAddress((void**)&xf, g_xf);
    cudaGetSymbolAddress((void**)&qf, g_qkvf);
    cudaGetSymbolAddress((void**)&of, g_of);
    cudaGetSymbolAddress((void**)&wqf, g_wqkvf);
    cudaGetSymbolAddress((void**)&wof, g_woutf);

    cudaFuncSetAttribute(gemm_f16<true>,
                         cudaFuncAttributeMaxDynamicSharedMemorySize, GSMEM);
    cudaFuncSetAttribute(gemm_f16<false>,
                         cudaFuncAttributeMaxDynamicSharedMemorySize, GSMEM);
    cudaFuncSetAttribute(attn_f16,
                         cudaFuncAttributeMaxDynamicSharedMemorySize, ASMEM);

    // 0) conversions
    cvt_f32_f16<<<(ROWS * DIM / 4 + 255) / 256, 256>>>(x, xf, ROWS * DIM / 4);
    transpose_cvt<<<dim3(QKV_COLS / 32, DIM / 32), dim3(32, 8)>>>(w_qkv, wqf, DIM, QKV_COLS);
    transpose_cvt<<<dim3(DIM / 32, INNER / 32), dim3(32, 8)>>>(w_out, wof, INNER, DIM);

    // 1) qkv = x @ w_qkv + b_qkv  (fp16 out)
    gemm_f16<true><<<dim3(QKV_COLS / GBN, ROWS / GBM), 256, GSMEM>>>(
        xf, wqf, b_qkv, nullptr, qf, ROWS, QKV_COLS, DIM);

    // 2) flash attention (fp16) -> fp16 [b n (h d)]
    attn_f16<<<dim3(SEQ / TQ, HEADS, BATCH), 256, ASMEM>>>(qf, of);

    // 3) out = attn @ w_out + b_out  (fp32 out)
    gemm_f16<false><<<dim3(DIM / GBN, ROWS / GBM), 256, GSMEM>>>(
        of, wof, b_out, out, nullptr, ROWS, DIM, INNER);
}